// round 12
// baseline (speedup 1.0000x reference)
#include <cuda_runtime.h>

#define N_NODES 100000
#define N_EDGES 3200000
#define NFEAT 128
#define HID 16
#define NC 10
#define NCP2 16   // h2 rows padded to 16 floats (64B, 4x float4)
#define NG 64
#define SCAN_BLK 1024
#define N_SCAN_BLOCKS ((N_NODES + SCAN_BLK - 1) / SCAN_BLK)   // 98

#define GEMM1_BLOCKS ((N_NODES + 63) / 64)          // 1563 = 3 * 521
#define PRE1_QUADS   (GEMM1_BLOCKS / 3)             // 521 (3 gemm + 1 hist per quad)
#define PRE1_BLOCKS  (PRE1_QUADS * 4)               // 2084

// ---------------- device scratch --------------------------------------------------
__device__ int   g_cnt_i   [N_NODES];      // in-degree histogram over dst (self-cleaned)
__device__ int   g_rowstart[N_NODES];      // exclusive prefix sum
__device__ int   g_rank    [N_EDGES];      // rank of edge within its dst row (from hist)
__device__ int   g_bsum    [N_SCAN_BLOCKS];
__device__ int2  g_csr     [N_EDGES];      // {src, __float_as_int(dinv[src])}
__device__ float g_dinv    [N_NODES];
__device__ float g_h1      [N_NODES * HID];    // x @ W1
__device__ float g_h2      [N_NODES * NCP2];   // relu(conv1) @ W2, padded
__device__ float g_pool    [NG * NC];          // self-cleaned in softmax
__device__ float g_gcnt    [NG];               // self-cleaned in softmax

// ---------------- fused: GEMM1 (3/4 of blocks) + dst-histogram/rank (1/4) -----------
__global__ __launch_bounds__(256) void k_pre1(const float* __restrict__ x,
                                              const float* __restrict__ W1,
                                              const int* __restrict__ ei) {
    __shared__ float sx[64 * 129];
    __shared__ float sW[NFEAT * HID];

    int b = blockIdx.x;
    int tid = threadIdx.x;

    if ((b & 3) == 3) {
        // ---- histogram role: also record per-edge rank (atomic return value) ----
        const int4* dst4 = reinterpret_cast<const int4*>(ei + N_EDGES);
        int4* rank4 = reinterpret_cast<int4*>(g_rank);
        int n4 = N_EDGES / 4;
        int i = (b >> 2) * 256 + tid;
        int stride = PRE1_QUADS * 256;
        for (; i < n4; i += stride) {
            int4 d = dst4[i];
            int4 r;
            r.x = atomicAdd(&g_cnt_i[d.x], 1);
            r.y = atomicAdd(&g_cnt_i[d.y], 1);
            r.z = atomicAdd(&g_cnt_i[d.z], 1);
            r.w = atomicAdd(&g_cnt_i[d.w], 1);
            rank4[i] = r;
        }
        return;
    }

    // ---- gemm1 role ----
    int gb = (b >> 2) * 3 + (b & 3);      // 0..GEMM1_BLOCKS-1
    int node0 = gb * 64;

    for (int j = tid; j < NFEAT * HID; j += 256) sW[j] = W1[j];

    int nvalid = N_NODES - node0; if (nvalid > 64) nvalid = 64;
    for (int j = tid; j < 64 * NFEAT; j += 256) {
        int r = j / NFEAT, c = j % NFEAT;
        sx[r * 129 + c] = (r < nvalid) ? x[(long long)(node0 + r) * NFEAT + c] : 0.f;
    }
    __syncthreads();

    int n  = tid & 63;
    int og = tid >> 6;
    if (n >= nvalid) return;

    float4 acc0 = make_float4(0.f, 0.f, 0.f, 0.f);
    float4 acc1 = make_float4(0.f, 0.f, 0.f, 0.f);
    const float4* sW4 = reinterpret_cast<const float4*>(sW);
    const float*  xr  = sx + n * 129;
#pragma unroll 8
    for (int k = 0; k < NFEAT; k += 2) {
        float xv0 = xr[k], xv1 = xr[k + 1];
        float4 w0 = sW4[k * 4 + og];
        float4 w1 = sW4[(k + 1) * 4 + og];
        acc0.x += xv0 * w0.x; acc0.y += xv0 * w0.y;
        acc0.z += xv0 * w0.z; acc0.w += xv0 * w0.w;
        acc1.x += xv1 * w1.x; acc1.y += xv1 * w1.y;
        acc1.z += xv1 * w1.z; acc1.w += xv1 * w1.w;
    }
    float4 acc = make_float4(acc0.x + acc1.x, acc0.y + acc1.y,
                             acc0.z + acc1.z, acc0.w + acc1.w);
    reinterpret_cast<float4*>(g_h1 + (node0 + n) * HID)[og] = acc;
}

// ---------------- scan phase 1 (+ dinv) ----------------------------------------------
__global__ __launch_bounds__(SCAN_BLK) void k_scan_block() {
    __shared__ int sh[SCAN_BLK];
    int t = threadIdx.x;
    int i = blockIdx.x * SCAN_BLK + t;
    int v = (i < N_NODES) ? g_cnt_i[i] : 0;
    if (i < N_NODES) g_dinv[i] = rsqrtf((float)v + 1.0f);
    sh[t] = v;
    __syncthreads();
#pragma unroll
    for (int off = 1; off < SCAN_BLK; off <<= 1) {
        int add = (t >= off) ? sh[t - off] : 0;
        __syncthreads();
        sh[t] += add;
        __syncthreads();
    }
    if (i < N_NODES) g_rowstart[i] = sh[t] - v;          // block-local exclusive
    if (t == SCAN_BLK - 1) g_bsum[blockIdx.x] = sh[t];
}

// ---------------- scan finish: per-block redundant bsum scan + offset -----------------
__global__ __launch_bounds__(256) void k_scan_finish() {
    __shared__ int sb[128];
    int t = threadIdx.x;
    if (t < 128) sb[t] = (t < N_SCAN_BLOCKS) ? g_bsum[t] : 0;
    __syncthreads();
#pragma unroll
    for (int off = 1; off < 128; off <<= 1) {
        int add = (t < 128 && t >= off) ? sb[t - off] : 0;
        __syncthreads();
        if (t < 128) sb[t] += add;
        __syncthreads();
    }
    int i = blockIdx.x * 256 + t;
    if (i < N_NODES) {
        int blk = i >> 10;
        int excl = sb[blk] - g_bsum[blk];       // inclusive -> exclusive
        g_rowstart[i] += excl;
    }
}

// ---------------- CSR fill: atomic-free (pos = rowstart[dst] + rank[e]) ----------------
__global__ __launch_bounds__(256) void k_fill(const int* __restrict__ ei) {
    const int4* s4p = reinterpret_cast<const int4*>(ei);
    const int4* d4p = reinterpret_cast<const int4*>(ei + N_EDGES);
    const int4* r4p = reinterpret_cast<const int4*>(g_rank);
    int i = blockIdx.x * blockDim.x + threadIdx.x;
    int n4 = N_EDGES / 4;
    if (i >= n4) return;
    int4 s = s4p[i];
    int4 d = d4p[i];
    int4 r = r4p[i];
    int p0 = g_rowstart[d.x] + r.x;
    int p1 = g_rowstart[d.y] + r.y;
    int p2 = g_rowstart[d.z] + r.z;
    int p3 = g_rowstart[d.w] + r.w;
    float a0 = g_dinv[s.x], a1 = g_dinv[s.y], a2 = g_dinv[s.z], a3 = g_dinv[s.w];
    g_csr[p0] = make_int2(s.x, __float_as_int(a0));
    g_csr[p1] = make_int2(s.y, __float_as_int(a1));
    g_csr[p2] = make_int2(s.z, __float_as_int(a2));
    g_csr[p3] = make_int2(s.w, __float_as_int(a3));
}

// ---------------- gather1 + combine1 + relu + GEMM2 (warp per node) --------------------
// 32 lanes = 8 edge-slots x 4 row-chunks; zero intra-warp degree divergence.
__global__ __launch_bounds__(256) void k_gather1(const float* __restrict__ b1,
                                                 const float* __restrict__ W2) {
    __shared__ float sW2[HID * NC];
    int tid = threadIdx.x;
    if (tid < HID * NC) sW2[tid] = W2[tid];
    __syncthreads();

    int lane = tid & 31;
    int node = blockIdx.x * 8 + (tid >> 5);
    if (node >= N_NODES) return;
    int e_slot = lane >> 2;      // 0..7
    int chunk  = lane & 3;       // 0..3

    int rs  = g_rowstart[node];
    int deg = g_cnt_i[node];
    float din = g_dinv[node];
    const int2* sp = g_csr + rs;

    float4 acc = make_float4(0.f, 0.f, 0.f, 0.f);
    int j = 0;
    for (; j + 16 <= deg; j += 16) {          // 16 edges per iter (2 batches in flight)
        int2 pa = sp[j + e_slot];
        int2 pb = sp[j + 8 + e_slot];
        float4 va = *reinterpret_cast<const float4*>(g_h1 + pa.x * HID + chunk * 4);
        float4 vb = *reinterpret_cast<const float4*>(g_h1 + pb.x * HID + chunk * 4);
        float ca = din * __int_as_float(pa.y);
        float cb = din * __int_as_float(pb.y);
        acc.x += va.x * ca; acc.y += va.y * ca; acc.z += va.z * ca; acc.w += va.w * ca;
        acc.x += vb.x * cb; acc.y += vb.y * cb; acc.z += vb.z * cb; acc.w += vb.w * cb;
    }
    if (j + 8 <= deg) {
        int2 p = sp[j + e_slot];
        float4 v = *reinterpret_cast<const float4*>(g_h1 + p.x * HID + chunk * 4);
        float c = din * __int_as_float(p.y);
        acc.x += v.x * c; acc.y += v.y * c; acc.z += v.z * c; acc.w += v.w * c;
        j += 8;
    }
    if (j + e_slot < deg) {                   // predicated tail (0..7 edges)
        int2 p = sp[j + e_slot];
        float4 v = *reinterpret_cast<const float4*>(g_h1 + p.x * HID + chunk * 4);
        float c = din * __int_as_float(p.y);
        acc.x += v.x * c; acc.y += v.y * c; acc.z += v.z * c; acc.w += v.w * c;
    }

    // reduce across the 8 edge-slots (lanes differing in bits 2..4)
#pragma unroll
    for (int m = 4; m <= 16; m <<= 1) {
        acc.x += __shfl_xor_sync(0xffffffffu, acc.x, m);
        acc.y += __shfl_xor_sync(0xffffffffu, acc.y, m);
        acc.z += __shfl_xor_sync(0xffffffffu, acc.z, m);
        acc.w += __shfl_xor_sync(0xffffffffu, acc.w, m);
    }

    // combine + relu (every lane now holds its chunk's full sum)
    float sl = din * din;
    float4 h = *reinterpret_cast<const float4*>(g_h1 + node * HID + chunk * 4);
    float4 b = reinterpret_cast<const float4*>(b1)[chunk];
    float4 a;
    a.x = fmaxf(acc.x + h.x * sl + b.x, 0.f);
    a.y = fmaxf(acc.y + h.y * sl + b.y, 0.f);
    a.z = fmaxf(acc.z + h.z * sl + b.z, 0.f);
    a.w = fmaxf(acc.w + h.w * sl + b.w, 0.f);

    // assemble the full 16-wide hr row in every lane (chunk q lives on lane q)
    float hr[HID];
#pragma unroll
    for (int q = 0; q < 4; q++) {
        hr[q * 4 + 0] = __shfl_sync(0xffffffffu, a.x, q);
        hr[q * 4 + 1] = __shfl_sync(0xffffffffu, a.y, q);
        hr[q * 4 + 2] = __shfl_sync(0xffffffffu, a.z, q);
        hr[q * 4 + 3] = __shfl_sync(0xffffffffu, a.w, q);
    }

    // gemm2: lane = output column; lanes 10..15 write zero pad
    float val = 0.f;
    if (lane < NC) {
        float s = 0.f;
#pragma unroll
        for (int k = 0; k < HID; k++) s += hr[k] * sW2[k * NC + lane];
        val = s;
    }
    if (lane < NCP2)
        g_h2[node * NCP2 + lane] = val;        // coalesced 64B row store
}

// ---------------- gather2 + combine2 + mean-pool (warp per node) -----------------------
__global__ __launch_bounds__(256) void k_gather2(const float* __restrict__ b2,
                                                 const int* __restrict__ batch) {
    int tid = threadIdx.x;
    int lane = tid & 31;
    int node = blockIdx.x * 8 + (tid >> 5);
    if (node >= N_NODES) return;
    int e_slot = lane >> 2;
    int chunk  = lane & 3;

    int rs  = g_rowstart[node];
    int deg = g_cnt_i[node];
    float din = g_dinv[node];
    const int2* sp = g_csr + rs;

    float4 acc = make_float4(0.f, 0.f, 0.f, 0.f);
    int j = 0;
    for (; j + 16 <= deg; j += 16) {
        int2 pa = sp[j + e_slot];
        int2 pb = sp[j + 8 + e_slot];
        float4 va = *reinterpret_cast<const float4*>(g_h2 + pa.x * NCP2 + chunk * 4);
        float4 vb = *reinterpret_cast<const float4*>(g_h2 + pb.x * NCP2 + chunk * 4);
        float ca = din * __int_as_float(pa.y);
        float cb = din * __int_as_float(pb.y);
        acc.x += va.x * ca; acc.y += va.y * ca; acc.z += va.z * ca; acc.w += va.w * ca;
        acc.x += vb.x * cb; acc.y += vb.y * cb; acc.z += vb.z * cb; acc.w += vb.w * cb;
    }
    if (j + 8 <= deg) {
        int2 p = sp[j + e_slot];
        float4 v = *reinterpret_cast<const float4*>(g_h2 + p.x * NCP2 + chunk * 4);
        float c = din * __int_as_float(p.y);
        acc.x += v.x * c; acc.y += v.y * c; acc.z += v.z * c; acc.w += v.w * c;
        j += 8;
    }
    if (j + e_slot < deg) {
        int2 p = sp[j + e_slot];
        float4 v = *reinterpret_cast<const float4*>(g_h2 + p.x * NCP2 + chunk * 4);
        float c = din * __int_as_float(p.y);
        acc.x += v.x * c; acc.y += v.y * c; acc.z += v.z * c; acc.w += v.w * c;
    }

#pragma unroll
    for (int m = 4; m <= 16; m <<= 1) {
        acc.x += __shfl_xor_sync(0xffffffffu, acc.x, m);
        acc.y += __shfl_xor_sync(0xffffffffu, acc.y, m);
        acc.z += __shfl_xor_sync(0xffffffffu, acc.z, m);
        acc.w += __shfl_xor_sync(0xffffffffu, acc.w, m);
    }

    float sl = din * din;
    float4 h = *reinterpret_cast<const float4*>(g_h2 + node * NCP2 + chunk * 4);
    int g = batch[node];

    float4 res;
    res.x = acc.x + h.x * sl;
    res.y = acc.y + h.y * sl;
    res.z = acc.z + h.z * sl;
    res.w = acc.w + h.w * sl;

    // lanes 0..2 (chunk==lane) commit cols [lane*4, ...) to the pool
    if (lane < 3) {
        float* pool = g_pool + g * NC;
        int base = lane * 4;
        atomicAdd(pool + base + 0, res.x + b2[base + 0]);
        atomicAdd(pool + base + 1, res.y + b2[base + 1]);
        if (base + 2 < NC) {
            atomicAdd(pool + base + 2, res.z + b2[base + 2]);
            atomicAdd(pool + base + 3, res.w + b2[base + 3]);
        }
    }
    if (lane == 0) {
        atomicAdd(&g_gcnt[g], 1.0f);
        g_cnt_i[node] = 0;                    // self-clean for next call
    }
}

// ---------------- finalize: mean + log_softmax (+ self-clean pool) ----------------------
__global__ void k_softmax(float* __restrict__ out) {
    int g = threadIdx.x;
    if (g >= NG) return;
    float cnt = fmaxf(g_gcnt[g], 1.0f);
    float p[NC];
    float m = -1e30f;
#pragma unroll
    for (int o = 0; o < NC; o++) { p[o] = g_pool[g * NC + o] / cnt; m = fmaxf(m, p[o]); }
    float s = 0.f;
#pragma unroll
    for (int o = 0; o < NC; o++) s += __expf(p[o] - m);
    float l = logf(s);
#pragma unroll
    for (int o = 0; o < NC; o++) {
        out[g * NC + o] = p[o] - m - l;
        g_pool[g * NC + o] = 0.f;             // self-clean for next call
    }
    g_gcnt[g] = 0.f;
}

// ---------------- launcher ----------------------------------------------------------------
extern "C" void kernel_launch(void* const* d_in, const int* in_sizes, int n_in,
                              void* d_out, int out_size) {
    const float* x     = (const float*)d_in[0];
    const int*   ei    = (const int*)d_in[1];    // int32 (jax default int)
    const int*   batch = (const int*)d_in[2];
    const float* W1    = (const float*)d_in[3];
    const float* b1    = (const float*)d_in[4];
    const float* W2    = (const float*)d_in[5];
    const float* b2    = (const float*)d_in[6];
    float* out = (float*)d_out;

    const int TB = 256;
    const int nodeBlocks   = (N_NODES + TB - 1) / TB;          // 391
    const int fillBlocks   = (N_EDGES / 4 + TB - 1) / TB;      // 3125
    const int gatherBlocks = (N_NODES + 7) / 8;                // 12500 (warp per node)

    k_pre1<<<PRE1_BLOCKS, TB>>>(x, W1, ei);           // launch 1
    k_scan_block<<<N_SCAN_BLOCKS, SCAN_BLK>>>();      // launch 2
    k_scan_finish<<<nodeBlocks, TB>>>();              // launch 3
    k_fill<<<fillBlocks, TB>>>(ei);                   // launch 4  <- ncu slot
    k_gather1<<<gatherBlocks, TB>>>(b1, W2);          // launch 5
    k_gather2<<<gatherBlocks, TB>>>(b2, batch);       // launch 6
    k_softmax<<<1, 64>>>(out);                        // launch 7
}

// round 13
// speedup vs baseline: 1.5087x; 1.5087x over previous
#include <cuda_runtime.h>

#define N_NODES 100000
#define N_EDGES 3200000
#define NFEAT 128
#define HID 16
#define NC 10
#define NCP2 16   // h2 rows padded to 16 floats (64B, 4x float4)
#define NG 64
#define SCAN_BLK 1024
#define N_SCAN_BLOCKS ((N_NODES + SCAN_BLK - 1) / SCAN_BLK)   // 98

#define GEMM1_BLOCKS ((N_NODES + 63) / 64)          // 1563 = 3 * 521
#define PRE1_QUADS   (GEMM1_BLOCKS / 3)             // 521 (3 gemm + 1 hist per quad)
#define PRE1_BLOCKS  (PRE1_QUADS * 4)               // 2084

// ---------------- device scratch --------------------------------------------------
__device__ int   g_cnt_i   [N_NODES];      // in-degree histogram over dst (self-cleaned)
__device__ int   g_rowstart[N_NODES];      // exclusive prefix sum
__device__ int   g_rank    [N_EDGES];      // rank of edge within its dst row (from hist)
__device__ int   g_bsum    [N_SCAN_BLOCKS];
__device__ int2  g_csr     [N_EDGES];      // {src, __float_as_int(dinv[src])}
__device__ float g_dinv    [N_NODES];
__device__ float g_h1      [N_NODES * HID];    // x @ W1
__device__ float g_h2      [N_NODES * NCP2];   // relu(conv1) @ W2, padded
__device__ float g_pool    [NG * NC];          // self-cleaned in softmax
__device__ float g_gcnt    [NG];               // self-cleaned in softmax

// ---------------- fused: GEMM1 (3/4 of blocks) + dst-histogram/rank (1/4) -----------
__global__ __launch_bounds__(256) void k_pre1(const float* __restrict__ x,
                                              const float* __restrict__ W1,
                                              const int* __restrict__ ei) {
    __shared__ float sx[64 * 129];
    __shared__ float sW[NFEAT * HID];

    int b = blockIdx.x;
    int tid = threadIdx.x;

    if ((b & 3) == 3) {
        // ---- histogram role: also record per-edge rank (atomic return value) ----
        const int4* dst4 = reinterpret_cast<const int4*>(ei + N_EDGES);
        int4* rank4 = reinterpret_cast<int4*>(g_rank);
        int n4 = N_EDGES / 4;
        int i = (b >> 2) * 256 + tid;
        int stride = PRE1_QUADS * 256;
        for (; i < n4; i += stride) {
            int4 d = dst4[i];
            int4 r;
            r.x = atomicAdd(&g_cnt_i[d.x], 1);
            r.y = atomicAdd(&g_cnt_i[d.y], 1);
            r.z = atomicAdd(&g_cnt_i[d.z], 1);
            r.w = atomicAdd(&g_cnt_i[d.w], 1);
            rank4[i] = r;
        }
        return;
    }

    // ---- gemm1 role ----
    int gb = (b >> 2) * 3 + (b & 3);      // 0..GEMM1_BLOCKS-1
    int node0 = gb * 64;

    for (int j = tid; j < NFEAT * HID; j += 256) sW[j] = W1[j];

    int nvalid = N_NODES - node0; if (nvalid > 64) nvalid = 64;
    for (int j = tid; j < 64 * NFEAT; j += 256) {
        int r = j / NFEAT, c = j % NFEAT;
        sx[r * 129 + c] = (r < nvalid) ? x[(long long)(node0 + r) * NFEAT + c] : 0.f;
    }
    __syncthreads();

    int n  = tid & 63;
    int og = tid >> 6;
    if (n >= nvalid) return;

    float4 acc0 = make_float4(0.f, 0.f, 0.f, 0.f);
    float4 acc1 = make_float4(0.f, 0.f, 0.f, 0.f);
    const float4* sW4 = reinterpret_cast<const float4*>(sW);
    const float*  xr  = sx + n * 129;
#pragma unroll 8
    for (int k = 0; k < NFEAT; k += 2) {
        float xv0 = xr[k], xv1 = xr[k + 1];
        float4 w0 = sW4[k * 4 + og];
        float4 w1 = sW4[(k + 1) * 4 + og];
        acc0.x += xv0 * w0.x; acc0.y += xv0 * w0.y;
        acc0.z += xv0 * w0.z; acc0.w += xv0 * w0.w;
        acc1.x += xv1 * w1.x; acc1.y += xv1 * w1.y;
        acc1.z += xv1 * w1.z; acc1.w += xv1 * w1.w;
    }
    float4 acc = make_float4(acc0.x + acc1.x, acc0.y + acc1.y,
                             acc0.z + acc1.z, acc0.w + acc1.w);
    reinterpret_cast<float4*>(g_h1 + (node0 + n) * HID)[og] = acc;
}

// ---------------- scan phase 1 (+ dinv) ----------------------------------------------
__global__ __launch_bounds__(SCAN_BLK) void k_scan_block() {
    __shared__ int sh[SCAN_BLK];
    int t = threadIdx.x;
    int i = blockIdx.x * SCAN_BLK + t;
    int v = (i < N_NODES) ? g_cnt_i[i] : 0;
    if (i < N_NODES) g_dinv[i] = rsqrtf((float)v + 1.0f);
    sh[t] = v;
    __syncthreads();
#pragma unroll
    for (int off = 1; off < SCAN_BLK; off <<= 1) {
        int add = (t >= off) ? sh[t - off] : 0;
        __syncthreads();
        sh[t] += add;
        __syncthreads();
    }
    if (i < N_NODES) g_rowstart[i] = sh[t] - v;          // block-local exclusive
    if (t == SCAN_BLK - 1) g_bsum[blockIdx.x] = sh[t];
}

// ---------------- scan finish: per-block redundant bsum scan + offset -----------------
__global__ __launch_bounds__(256) void k_scan_finish() {
    __shared__ int sb[128];
    int t = threadIdx.x;
    if (t < 128) sb[t] = (t < N_SCAN_BLOCKS) ? g_bsum[t] : 0;
    __syncthreads();
#pragma unroll
    for (int off = 1; off < 128; off <<= 1) {
        int add = (t < 128 && t >= off) ? sb[t - off] : 0;
        __syncthreads();
        if (t < 128) sb[t] += add;
        __syncthreads();
    }
    int i = blockIdx.x * 256 + t;
    if (i < N_NODES) {
        int blk = i >> 10;
        int excl = sb[blk] - g_bsum[blk];       // inclusive -> exclusive
        g_rowstart[i] += excl;
    }
}

// ---------------- CSR fill: atomic-free (pos = rowstart[dst] + rank[e]) ----------------
__global__ __launch_bounds__(256) void k_fill(const int* __restrict__ ei) {
    const int4* s4p = reinterpret_cast<const int4*>(ei);
    const int4* d4p = reinterpret_cast<const int4*>(ei + N_EDGES);
    const int4* r4p = reinterpret_cast<const int4*>(g_rank);
    int i = blockIdx.x * blockDim.x + threadIdx.x;
    int n4 = N_EDGES / 4;
    if (i >= n4) return;
    int4 s = s4p[i];
    int4 d = d4p[i];
    int4 r = r4p[i];
    int p0 = g_rowstart[d.x] + r.x;
    int p1 = g_rowstart[d.y] + r.y;
    int p2 = g_rowstart[d.z] + r.z;
    int p3 = g_rowstart[d.w] + r.w;
    float a0 = g_dinv[s.x], a1 = g_dinv[s.y], a2 = g_dinv[s.z], a3 = g_dinv[s.w];
    g_csr[p0] = make_int2(s.x, __float_as_int(a0));
    g_csr[p1] = make_int2(s.y, __float_as_int(a1));
    g_csr[p2] = make_int2(s.z, __float_as_int(a2));
    g_csr[p3] = make_int2(s.w, __float_as_int(a3));
}

// ---------------- gather1 + combine1 + relu + GEMM2 (4 threads / node, pipelined) ------
__global__ __launch_bounds__(256) void k_gather1(const float* __restrict__ b1,
                                                 const float* __restrict__ W2) {
    __shared__ float sW2[HID * NC];
    int tid = threadIdx.x;
    if (tid < HID * NC) sW2[tid] = W2[tid];
    __syncthreads();

    int gt = blockIdx.x * blockDim.x + tid;
    int node = gt >> 2;
    bool valid = node < N_NODES;
    if (!valid) node = N_NODES - 1;          // clamp; keep lanes alive for shfl
    int part = tid & 3;

    int rs  = g_rowstart[node];
    int deg = g_cnt_i[node];
    float din = g_dinv[node];

    const int2* sp = g_csr + rs;
    float4 acc = make_float4(0.f, 0.f, 0.f, 0.f);

    // software-pipelined: CSR entries for next iter load during current iter's rows/FMA
    int j = 0;
    int2 p0, p1, p2, p3;
    if (deg >= 4) { p0 = sp[0]; p1 = sp[1]; p2 = sp[2]; p3 = sp[3]; }
    for (; j + 8 <= deg; j += 4) {
        float4 v0 = *reinterpret_cast<const float4*>(g_h1 + p0.x * HID + part * 4);
        float4 v1 = *reinterpret_cast<const float4*>(g_h1 + p1.x * HID + part * 4);
        float4 v2 = *reinterpret_cast<const float4*>(g_h1 + p2.x * HID + part * 4);
        float4 v3 = *reinterpret_cast<const float4*>(g_h1 + p3.x * HID + part * 4);
        int2 q0 = sp[j + 4], q1 = sp[j + 5], q2 = sp[j + 6], q3 = sp[j + 7];
        float c0 = din * __int_as_float(p0.y);
        float c1 = din * __int_as_float(p1.y);
        float c2 = din * __int_as_float(p2.y);
        float c3 = din * __int_as_float(p3.y);
        acc.x += v0.x * c0; acc.y += v0.y * c0; acc.z += v0.z * c0; acc.w += v0.w * c0;
        acc.x += v1.x * c1; acc.y += v1.y * c1; acc.z += v1.z * c1; acc.w += v1.w * c1;
        acc.x += v2.x * c2; acc.y += v2.y * c2; acc.z += v2.z * c2; acc.w += v2.w * c2;
        acc.x += v3.x * c3; acc.y += v3.y * c3; acc.z += v3.z * c3; acc.w += v3.w * c3;
        p0 = q0; p1 = q1; p2 = q2; p3 = q3;
    }
    if (j + 4 <= deg) {
        float4 v0 = *reinterpret_cast<const float4*>(g_h1 + p0.x * HID + part * 4);
        float4 v1 = *reinterpret_cast<const float4*>(g_h1 + p1.x * HID + part * 4);
        float4 v2 = *reinterpret_cast<const float4*>(g_h1 + p2.x * HID + part * 4);
        float4 v3 = *reinterpret_cast<const float4*>(g_h1 + p3.x * HID + part * 4);
        float c0 = din * __int_as_float(p0.y);
        float c1 = din * __int_as_float(p1.y);
        float c2 = din * __int_as_float(p2.y);
        float c3 = din * __int_as_float(p3.y);
        acc.x += v0.x * c0; acc.y += v0.y * c0; acc.z += v0.z * c0; acc.w += v0.w * c0;
        acc.x += v1.x * c1; acc.y += v1.y * c1; acc.z += v1.z * c1; acc.w += v1.w * c1;
        acc.x += v2.x * c2; acc.y += v2.y * c2; acc.z += v2.z * c2; acc.w += v2.w * c2;
        acc.x += v3.x * c3; acc.y += v3.y * c3; acc.z += v3.z * c3; acc.w += v3.w * c3;
        j += 4;
    }
    for (; j < deg; j++) {
        int2 p = sp[j];
        float c = din * __int_as_float(p.y);
        float4 v = *reinterpret_cast<const float4*>(g_h1 + p.x * HID + part * 4);
        acc.x += v.x * c; acc.y += v.y * c; acc.z += v.z * c; acc.w += v.w * c;
    }

    // combine + relu -> this thread's 4-wide slice of hr
    float sl = din * din;
    float4 h = *reinterpret_cast<const float4*>(g_h1 + node * HID + part * 4);
    float4 b = reinterpret_cast<const float4*>(b1)[part];
    float4 a;
    a.x = fmaxf(acc.x + h.x * sl + b.x, 0.f);
    a.y = fmaxf(acc.y + h.y * sl + b.y, 0.f);
    a.z = fmaxf(acc.z + h.z * sl + b.z, 0.f);
    a.w = fmaxf(acc.w + h.w * sl + b.w, 0.f);

    // exchange the 16-wide hr row among the 4 lanes of this node
    float hr[HID];
    unsigned lanebase = (unsigned)(tid & 31) & ~3u;
#pragma unroll
    for (int q = 0; q < 4; q++) {
        hr[q * 4 + 0] = __shfl_sync(0xffffffffu, a.x, lanebase + q);
        hr[q * 4 + 1] = __shfl_sync(0xffffffffu, a.y, lanebase + q);
        hr[q * 4 + 2] = __shfl_sync(0xffffffffu, a.z, lanebase + q);
        hr[q * 4 + 3] = __shfl_sync(0xffffffffu, a.w, lanebase + q);
    }

    // gemm2: this thread computes output cols [part*4, part*4+4)
    float4 o = make_float4(0.f, 0.f, 0.f, 0.f);
    float* op = &o.x;
#pragma unroll
    for (int c = 0; c < 4; c++) {
        int col = part * 4 + c;
        if (col < NC) {
            float s = 0.f;
#pragma unroll
            for (int k = 0; k < HID; k++) s += hr[k] * sW2[k * NC + col];
            op[c] = s;
        }
    }
    if (valid)
        *reinterpret_cast<float4*>(g_h2 + node * NCP2 + part * 4) = o;
}

// ---------------- gather2 + combine2 + mean-pool (4 threads / node, pipelined) ---------
__global__ __launch_bounds__(256) void k_gather2(const float* __restrict__ b2,
                                                 const int* __restrict__ batch) {
    int gt = blockIdx.x * blockDim.x + threadIdx.x;
    int node = gt >> 2;
    if (node >= N_NODES) return;
    int part = gt & 3;

    int rs  = g_rowstart[node];
    int deg = g_cnt_i[node];
    float din = g_dinv[node];
    int g = batch[node];

    const int2* sp = g_csr + rs;
    float4 acc = make_float4(0.f, 0.f, 0.f, 0.f);

    int j = 0;
    int2 p0, p1, p2, p3;
    if (deg >= 4) { p0 = sp[0]; p1 = sp[1]; p2 = sp[2]; p3 = sp[3]; }
    for (; j + 8 <= deg; j += 4) {
        float4 v0 = *reinterpret_cast<const float4*>(g_h2 + p0.x * NCP2 + part * 4);
        float4 v1 = *reinterpret_cast<const float4*>(g_h2 + p1.x * NCP2 + part * 4);
        float4 v2 = *reinterpret_cast<const float4*>(g_h2 + p2.x * NCP2 + part * 4);
        float4 v3 = *reinterpret_cast<const float4*>(g_h2 + p3.x * NCP2 + part * 4);
        int2 q0 = sp[j + 4], q1 = sp[j + 5], q2 = sp[j + 6], q3 = sp[j + 7];
        float c0 = din * __int_as_float(p0.y);
        float c1 = din * __int_as_float(p1.y);
        float c2 = din * __int_as_float(p2.y);
        float c3 = din * __int_as_float(p3.y);
        acc.x += v0.x * c0; acc.y += v0.y * c0; acc.z += v0.z * c0; acc.w += v0.w * c0;
        acc.x += v1.x * c1; acc.y += v1.y * c1; acc.z += v1.z * c1; acc.w += v1.w * c1;
        acc.x += v2.x * c2; acc.y += v2.y * c2; acc.z += v2.z * c2; acc.w += v2.w * c2;
        acc.x += v3.x * c3; acc.y += v3.y * c3; acc.z += v3.z * c3; acc.w += v3.w * c3;
        p0 = q0; p1 = q1; p2 = q2; p3 = q3;
    }
    if (j + 4 <= deg) {
        float4 v0 = *reinterpret_cast<const float4*>(g_h2 + p0.x * NCP2 + part * 4);
        float4 v1 = *reinterpret_cast<const float4*>(g_h2 + p1.x * NCP2 + part * 4);
        float4 v2 = *reinterpret_cast<const float4*>(g_h2 + p2.x * NCP2 + part * 4);
        float4 v3 = *reinterpret_cast<const float4*>(g_h2 + p3.x * NCP2 + part * 4);
        float c0 = din * __int_as_float(p0.y);
        float c1 = din * __int_as_float(p1.y);
        float c2 = din * __int_as_float(p2.y);
        float c3 = din * __int_as_float(p3.y);
        acc.x += v0.x * c0; acc.y += v0.y * c0; acc.z += v0.z * c0; acc.w += v0.w * c0;
        acc.x += v1.x * c1; acc.y += v1.y * c1; acc.z += v1.z * c1; acc.w += v1.w * c1;
        acc.x += v2.x * c2; acc.y += v2.y * c2; acc.z += v2.z * c2; acc.w += v2.w * c2;
        acc.x += v3.x * c3; acc.y += v3.y * c3; acc.z += v3.z * c3; acc.w += v3.w * c3;
        j += 4;
    }
    for (; j < deg; j++) {
        int2 p = sp[j];
        float c = din * __int_as_float(p.y);
        float4 v = *reinterpret_cast<const float4*>(g_h2 + p.x * NCP2 + part * 4);
        acc.x += v.x * c; acc.y += v.y * c; acc.z += v.z * c; acc.w += v.w * c;
    }

    float sl = din * din;
    float4 h = *reinterpret_cast<const float4*>(g_h2 + node * NCP2 + part * 4);
    float* pool = g_pool + g * NC;

    float res[4] = { acc.x + h.x * sl, acc.y + h.y * sl,
                     acc.z + h.z * sl, acc.w + h.w * sl };
#pragma unroll
    for (int c = 0; c < 4; c++) {
        int col = part * 4 + c;
        if (col < NC) atomicAdd(pool + col, res[c] + b2[col]);
    }
    if (part == 0) {
        atomicAdd(&g_gcnt[g], 1.0f);
        g_cnt_i[node] = 0;                    // self-clean for next call
    }
}

// ---------------- finalize: mean + log_softmax (+ self-clean pool) ----------------------
__global__ void k_softmax(float* __restrict__ out) {
    int g = threadIdx.x;
    if (g >= NG) return;
    float cnt = fmaxf(g_gcnt[g], 1.0f);
    float p[NC];
    float m = -1e30f;
#pragma unroll
    for (int o = 0; o < NC; o++) { p[o] = g_pool[g * NC + o] / cnt; m = fmaxf(m, p[o]); }
    float s = 0.f;
#pragma unroll
    for (int o = 0; o < NC; o++) s += __expf(p[o] - m);
    float l = logf(s);
#pragma unroll
    for (int o = 0; o < NC; o++) {
        out[g * NC + o] = p[o] - m - l;
        g_pool[g * NC + o] = 0.f;             // self-clean for next call
    }
    g_gcnt[g] = 0.f;
}

// ---------------- launcher ----------------------------------------------------------------
extern "C" void kernel_launch(void* const* d_in, const int* in_sizes, int n_in,
                              void* d_out, int out_size) {
    const float* x     = (const float*)d_in[0];
    const int*   ei    = (const int*)d_in[1];    // int32 (jax default int)
    const int*   batch = (const int*)d_in[2];
    const float* W1    = (const float*)d_in[3];
    const float* b1    = (const float*)d_in[4];
    const float* W2    = (const float*)d_in[5];
    const float* b2    = (const float*)d_in[6];
    float* out = (float*)d_out;

    const int TB = 256;
    const int nodeBlocks  = (N_NODES + TB - 1) / TB;          // 391
    const int node4Blocks = (4 * N_NODES + TB - 1) / TB;      // 1563
    const int fillBlocks  = (N_EDGES / 4 + TB - 1) / TB;      // 3125

    k_pre1<<<PRE1_BLOCKS, TB>>>(x, W1, ei);           // launch 1
    k_scan_block<<<N_SCAN_BLOCKS, SCAN_BLK>>>();      // launch 2
    k_scan_finish<<<nodeBlocks, TB>>>();              // launch 3
    k_fill<<<fillBlocks, TB>>>(ei);                   // launch 4  <- ncu slot
    k_gather1<<<node4Blocks, TB>>>(b1, W2);           // launch 5
    k_gather2<<<node4Blocks, TB>>>(b2, batch);        // launch 6
    k_softmax<<<1, 64>>>(out);                        // launch 7
}

// round 14
// speedup vs baseline: 1.7596x; 1.1663x over previous
#include <cuda_runtime.h>

#define N_NODES 100000
#define N_EDGES 3200000
#define NFEAT 128
#define HID 16
#define NC 10
#define NCP2 16   // h2 rows padded to 16 floats (64B, 4x float4)
#define NG 64
#define SCAN_BLK 1024
#define N_SCAN_BLOCKS ((N_NODES + SCAN_BLK - 1) / SCAN_BLK)   // 98

#define GEMM1_BLOCKS ((N_NODES + 63) / 64)          // 1563 = 3 * 521
#define PRE1_QUADS   (GEMM1_BLOCKS / 3)             // 521 (3 gemm + 1 hist per quad)
#define PRE1_BLOCKS  (PRE1_QUADS * 4)               // 2084

// ---------------- device scratch --------------------------------------------------
__device__ int   g_cnt_i   [N_NODES];      // in-degree histogram over dst (self-cleaned)
__device__ int   g_rowstart[N_NODES];      // exclusive prefix sum
__device__ int   g_cur     [N_NODES];      // fill cursors (re-inited each call)
__device__ int   g_bsum    [N_SCAN_BLOCKS];
__device__ int2  g_csr     [N_EDGES];      // {src, __float_as_int(dinv[src])}
__device__ float g_dinv    [N_NODES];
__device__ float g_h1      [N_NODES * HID];    // x @ W1
__device__ float g_h2      [N_NODES * NCP2];   // relu(conv1) @ W2, padded
__device__ float g_pool    [NG * NC];          // self-cleaned in softmax
__device__ float g_gcnt    [NG];               // self-cleaned in softmax

// ---------------- fused: GEMM1 (3/4 of blocks) + dst-histogram (1/4) ---------------
// R11 form: hist atomics are fire-and-forget (REDG), return value unused.
__global__ __launch_bounds__(256) void k_pre1(const float* __restrict__ x,
                                              const float* __restrict__ W1,
                                              const int* __restrict__ ei) {
    __shared__ float sx[64 * 129];
    __shared__ float sW[NFEAT * HID];

    int b = blockIdx.x;
    int tid = threadIdx.x;

    if ((b & 3) == 3) {
        // ---- histogram role: grid-stride over dst half as int4 ----
        const int4* dst4 = reinterpret_cast<const int4*>(ei + N_EDGES);
        int n4 = N_EDGES / 4;
        int i = (b >> 2) * 256 + tid;
        int stride = PRE1_QUADS * 256;
        for (; i < n4; i += stride) {
            int4 d = dst4[i];
            atomicAdd(&g_cnt_i[d.x], 1);
            atomicAdd(&g_cnt_i[d.y], 1);
            atomicAdd(&g_cnt_i[d.z], 1);
            atomicAdd(&g_cnt_i[d.w], 1);
        }
        return;
    }

    // ---- gemm1 role ----
    int gb = (b >> 2) * 3 + (b & 3);      // 0..GEMM1_BLOCKS-1
    int node0 = gb * 64;

    for (int j = tid; j < NFEAT * HID; j += 256) sW[j] = W1[j];

    int nvalid = N_NODES - node0; if (nvalid > 64) nvalid = 64;
    for (int j = tid; j < 64 * NFEAT; j += 256) {
        int r = j / NFEAT, c = j % NFEAT;
        sx[r * 129 + c] = (r < nvalid) ? x[(long long)(node0 + r) * NFEAT + c] : 0.f;
    }
    __syncthreads();

    int n  = tid & 63;
    int og = tid >> 6;
    if (n >= nvalid) return;

    float4 acc0 = make_float4(0.f, 0.f, 0.f, 0.f);
    float4 acc1 = make_float4(0.f, 0.f, 0.f, 0.f);
    const float4* sW4 = reinterpret_cast<const float4*>(sW);
    const float*  xr  = sx + n * 129;
#pragma unroll 8
    for (int k = 0; k < NFEAT; k += 2) {
        float xv0 = xr[k], xv1 = xr[k + 1];
        float4 w0 = sW4[k * 4 + og];
        float4 w1 = sW4[(k + 1) * 4 + og];
        acc0.x += xv0 * w0.x; acc0.y += xv0 * w0.y;
        acc0.z += xv0 * w0.z; acc0.w += xv0 * w0.w;
        acc1.x += xv1 * w1.x; acc1.y += xv1 * w1.y;
        acc1.z += xv1 * w1.z; acc1.w += xv1 * w1.w;
    }
    float4 acc = make_float4(acc0.x + acc1.x, acc0.y + acc1.y,
                             acc0.z + acc1.z, acc0.w + acc1.w);
    reinterpret_cast<float4*>(g_h1 + (node0 + n) * HID)[og] = acc;
}

// ---------------- scan phase 1 (+ dinv) ----------------------------------------------
__global__ __launch_bounds__(SCAN_BLK) void k_scan_block() {
    __shared__ int sh[SCAN_BLK];
    int t = threadIdx.x;
    int i = blockIdx.x * SCAN_BLK + t;
    int v = (i < N_NODES) ? g_cnt_i[i] : 0;
    if (i < N_NODES) g_dinv[i] = rsqrtf((float)v + 1.0f);
    sh[t] = v;
    __syncthreads();
#pragma unroll
    for (int off = 1; off < SCAN_BLK; off <<= 1) {
        int add = (t >= off) ? sh[t - off] : 0;
        __syncthreads();
        sh[t] += add;
        __syncthreads();
    }
    if (i < N_NODES) g_rowstart[i] = sh[t] - v;          // block-local exclusive
    if (t == SCAN_BLK - 1) g_bsum[blockIdx.x] = sh[t];
}

// ---------------- scan finish: per-block redundant bsum scan + offset + cursor init ---
__global__ __launch_bounds__(256) void k_scan_finish() {
    __shared__ int sb[128];
    int t = threadIdx.x;
    if (t < 128) sb[t] = (t < N_SCAN_BLOCKS) ? g_bsum[t] : 0;
    __syncthreads();
#pragma unroll
    for (int off = 1; off < 128; off <<= 1) {
        int add = (t < 128 && t >= off) ? sb[t - off] : 0;
        __syncthreads();
        if (t < 128) sb[t] += add;
        __syncthreads();
    }
    int i = blockIdx.x * 256 + t;
    if (i < N_NODES) {
        int blk = i >> 10;
        int excl = sb[blk] - g_bsum[blk];       // inclusive -> exclusive
        int rs = g_rowstart[i] + excl;
        g_rowstart[i] = rs;
        g_cur[i] = rs;
    }
}

// ---------------- CSR fill: 4 edges/thread via int4 (MLP=4), cursor atomics ------------
__global__ __launch_bounds__(256) void k_fill(const int* __restrict__ ei) {
    const int4* s4p = reinterpret_cast<const int4*>(ei);
    const int4* d4p = reinterpret_cast<const int4*>(ei + N_EDGES);
    int i = blockIdx.x * blockDim.x + threadIdx.x;
    int n4 = N_EDGES / 4;
    if (i >= n4) return;
    int4 s = s4p[i];
    int4 d = d4p[i];
    float a0 = g_dinv[s.x], a1 = g_dinv[s.y], a2 = g_dinv[s.z], a3 = g_dinv[s.w];
    int p0 = atomicAdd(&g_cur[d.x], 1);
    int p1 = atomicAdd(&g_cur[d.y], 1);
    int p2 = atomicAdd(&g_cur[d.z], 1);
    int p3 = atomicAdd(&g_cur[d.w], 1);
    g_csr[p0] = make_int2(s.x, __float_as_int(a0));
    g_csr[p1] = make_int2(s.y, __float_as_int(a1));
    g_csr[p2] = make_int2(s.z, __float_as_int(a2));
    g_csr[p3] = make_int2(s.w, __float_as_int(a3));
}

// ---------------- gather1 + combine1 + relu + GEMM2 (4 threads / node, pipelined) ------
__global__ __launch_bounds__(256) void k_gather1(const float* __restrict__ b1,
                                                 const float* __restrict__ W2) {
    __shared__ float sW2[HID * NC];
    int tid = threadIdx.x;
    if (tid < HID * NC) sW2[tid] = W2[tid];
    __syncthreads();

    int gt = blockIdx.x * blockDim.x + tid;
    int node = gt >> 2;
    bool valid = node < N_NODES;
    if (!valid) node = N_NODES - 1;          // clamp; keep lanes alive for shfl
    int part = tid & 3;

    int rs  = g_rowstart[node];
    int deg = g_cnt_i[node];
    float din = g_dinv[node];

    const int2* sp = g_csr + rs;
    float4 acc = make_float4(0.f, 0.f, 0.f, 0.f);

    // software-pipelined: CSR entries for next iter load during current iter's rows/FMA
    int j = 0;
    int2 p0, p1, p2, p3;
    if (deg >= 4) { p0 = sp[0]; p1 = sp[1]; p2 = sp[2]; p3 = sp[3]; }
    for (; j + 8 <= deg; j += 4) {
        float4 v0 = *reinterpret_cast<const float4*>(g_h1 + p0.x * HID + part * 4);
        float4 v1 = *reinterpret_cast<const float4*>(g_h1 + p1.x * HID + part * 4);
        float4 v2 = *reinterpret_cast<const float4*>(g_h1 + p2.x * HID + part * 4);
        float4 v3 = *reinterpret_cast<const float4*>(g_h1 + p3.x * HID + part * 4);
        int2 q0 = sp[j + 4], q1 = sp[j + 5], q2 = sp[j + 6], q3 = sp[j + 7];
        float c0 = din * __int_as_float(p0.y);
        float c1 = din * __int_as_float(p1.y);
        float c2 = din * __int_as_float(p2.y);
        float c3 = din * __int_as_float(p3.y);
        acc.x += v0.x * c0; acc.y += v0.y * c0; acc.z += v0.z * c0; acc.w += v0.w * c0;
        acc.x += v1.x * c1; acc.y += v1.y * c1; acc.z += v1.z * c1; acc.w += v1.w * c1;
        acc.x += v2.x * c2; acc.y += v2.y * c2; acc.z += v2.z * c2; acc.w += v2.w * c2;
        acc.x += v3.x * c3; acc.y += v3.y * c3; acc.z += v3.z * c3; acc.w += v3.w * c3;
        p0 = q0; p1 = q1; p2 = q2; p3 = q3;
    }
    if (j + 4 <= deg) {
        float4 v0 = *reinterpret_cast<const float4*>(g_h1 + p0.x * HID + part * 4);
        float4 v1 = *reinterpret_cast<const float4*>(g_h1 + p1.x * HID + part * 4);
        float4 v2 = *reinterpret_cast<const float4*>(g_h1 + p2.x * HID + part * 4);
        float4 v3 = *reinterpret_cast<const float4*>(g_h1 + p3.x * HID + part * 4);
        float c0 = din * __int_as_float(p0.y);
        float c1 = din * __int_as_float(p1.y);
        float c2 = din * __int_as_float(p2.y);
        float c3 = din * __int_as_float(p3.y);
        acc.x += v0.x * c0; acc.y += v0.y * c0; acc.z += v0.z * c0; acc.w += v0.w * c0;
        acc.x += v1.x * c1; acc.y += v1.y * c1; acc.z += v1.z * c1; acc.w += v1.w * c1;
        acc.x += v2.x * c2; acc.y += v2.y * c2; acc.z += v2.z * c2; acc.w += v2.w * c2;
        acc.x += v3.x * c3; acc.y += v3.y * c3; acc.z += v3.z * c3; acc.w += v3.w * c3;
        j += 4;
    }
    for (; j < deg; j++) {
        int2 p = sp[j];
        float c = din * __int_as_float(p.y);
        float4 v = *reinterpret_cast<const float4*>(g_h1 + p.x * HID + part * 4);
        acc.x += v.x * c; acc.y += v.y * c; acc.z += v.z * c; acc.w += v.w * c;
    }

    // combine + relu -> this thread's 4-wide slice of hr
    float sl = din * din;
    float4 h = *reinterpret_cast<const float4*>(g_h1 + node * HID + part * 4);
    float4 b = reinterpret_cast<const float4*>(b1)[part];
    float4 a;
    a.x = fmaxf(acc.x + h.x * sl + b.x, 0.f);
    a.y = fmaxf(acc.y + h.y * sl + b.y, 0.f);
    a.z = fmaxf(acc.z + h.z * sl + b.z, 0.f);
    a.w = fmaxf(acc.w + h.w * sl + b.w, 0.f);

    // exchange the 16-wide hr row among the 4 lanes of this node
    float hr[HID];
    unsigned lanebase = (unsigned)(tid & 31) & ~3u;
#pragma unroll
    for (int q = 0; q < 4; q++) {
        hr[q * 4 + 0] = __shfl_sync(0xffffffffu, a.x, lanebase + q);
        hr[q * 4 + 1] = __shfl_sync(0xffffffffu, a.y, lanebase + q);
        hr[q * 4 + 2] = __shfl_sync(0xffffffffu, a.z, lanebase + q);
        hr[q * 4 + 3] = __shfl_sync(0xffffffffu, a.w, lanebase + q);
    }

    // gemm2: this thread computes output cols [part*4, part*4+4)
    float4 o = make_float4(0.f, 0.f, 0.f, 0.f);
    float* op = &o.x;
#pragma unroll
    for (int c = 0; c < 4; c++) {
        int col = part * 4 + c;
        if (col < NC) {
            float s = 0.f;
#pragma unroll
            for (int k = 0; k < HID; k++) s += hr[k] * sW2[k * NC + col];
            op[c] = s;
        }
    }
    if (valid)
        *reinterpret_cast<float4*>(g_h2 + node * NCP2 + part * 4) = o;
}

// ---------------- gather2 + combine2 + mean-pool (4 threads / node, 8-deep pipeline) ---
__global__ __launch_bounds__(256) void k_gather2(const float* __restrict__ b2,
                                                 const int* __restrict__ batch) {
    int gt = blockIdx.x * blockDim.x + threadIdx.x;
    int node = gt >> 2;
    if (node >= N_NODES) return;
    int part = gt & 3;

    int rs  = g_rowstart[node];
    int deg = g_cnt_i[node];
    float din = g_dinv[node];
    int g = batch[node];

    const int2* sp = g_csr + rs;
    float4 acc = make_float4(0.f, 0.f, 0.f, 0.f);

    int j = 0;
    // ---- 8-deep main loop: 8 independent row loads in flight per thread ----
    for (; j + 16 <= deg; j += 8) {
        int2 p0 = sp[j + 0], p1 = sp[j + 1], p2 = sp[j + 2], p3 = sp[j + 3];
        int2 p4 = sp[j + 4], p5 = sp[j + 5], p6 = sp[j + 6], p7 = sp[j + 7];
        float4 v0 = *reinterpret_cast<const float4*>(g_h2 + p0.x * NCP2 + part * 4);
        float4 v1 = *reinterpret_cast<const float4*>(g_h2 + p1.x * NCP2 + part * 4);
        float4 v2 = *reinterpret_cast<const float4*>(g_h2 + p2.x * NCP2 + part * 4);
        float4 v3 = *reinterpret_cast<const float4*>(g_h2 + p3.x * NCP2 + part * 4);
        float4 v4 = *reinterpret_cast<const float4*>(g_h2 + p4.x * NCP2 + part * 4);
        float4 v5 = *reinterpret_cast<const float4*>(g_h2 + p5.x * NCP2 + part * 4);
        float4 v6 = *reinterpret_cast<const float4*>(g_h2 + p6.x * NCP2 + part * 4);
        float4 v7 = *reinterpret_cast<const float4*>(g_h2 + p7.x * NCP2 + part * 4);
        float c0 = din * __int_as_float(p0.y);
        float c1 = din * __int_as_float(p1.y);
        float c2 = din * __int_as_float(p2.y);
        float c3 = din * __int_as_float(p3.y);
        float c4 = din * __int_as_float(p4.y);
        float c5 = din * __int_as_float(p5.y);
        float c6 = din * __int_as_float(p6.y);
        float c7 = din * __int_as_float(p7.y);
        acc.x += v0.x * c0; acc.y += v0.y * c0; acc.z += v0.z * c0; acc.w += v0.w * c0;
        acc.x += v1.x * c1; acc.y += v1.y * c1; acc.z += v1.z * c1; acc.w += v1.w * c1;
        acc.x += v2.x * c2; acc.y += v2.y * c2; acc.z += v2.z * c2; acc.w += v2.w * c2;
        acc.x += v3.x * c3; acc.y += v3.y * c3; acc.z += v3.z * c3; acc.w += v3.w * c3;
        acc.x += v4.x * c4; acc.y += v4.y * c4; acc.z += v4.z * c4; acc.w += v4.w * c4;
        acc.x += v5.x * c5; acc.y += v5.y * c5; acc.z += v5.z * c5; acc.w += v5.w * c5;
        acc.x += v6.x * c6; acc.y += v6.y * c6; acc.z += v6.z * c6; acc.w += v6.w * c6;
        acc.x += v7.x * c7; acc.y += v7.y * c7; acc.z += v7.z * c7; acc.w += v7.w * c7;
    }
    // ---- 4-wide cleanup ----
    for (; j + 4 <= deg; j += 4) {
        int2 p0 = sp[j + 0], p1 = sp[j + 1], p2 = sp[j + 2], p3 = sp[j + 3];
        float4 v0 = *reinterpret_cast<const float4*>(g_h2 + p0.x * NCP2 + part * 4);
        float4 v1 = *reinterpret_cast<const float4*>(g_h2 + p1.x * NCP2 + part * 4);
        float4 v2 = *reinterpret_cast<const float4*>(g_h2 + p2.x * NCP2 + part * 4);
        float4 v3 = *reinterpret_cast<const float4*>(g_h2 + p3.x * NCP2 + part * 4);
        float c0 = din * __int_as_float(p0.y);
        float c1 = din * __int_as_float(p1.y);
        float c2 = din * __int_as_float(p2.y);
        float c3 = din * __int_as_float(p3.y);
        acc.x += v0.x * c0; acc.y += v0.y * c0; acc.z += v0.z * c0; acc.w += v0.w * c0;
        acc.x += v1.x * c1; acc.y += v1.y * c1; acc.z += v1.z * c1; acc.w += v1.w * c1;
        acc.x += v2.x * c2; acc.y += v2.y * c2; acc.z += v2.z * c2; acc.w += v2.w * c2;
        acc.x += v3.x * c3; acc.y += v3.y * c3; acc.z += v3.z * c3; acc.w += v3.w * c3;
    }
    for (; j < deg; j++) {
        int2 p = sp[j];
        float c = din * __int_as_float(p.y);
        float4 v = *reinterpret_cast<const float4*>(g_h2 + p.x * NCP2 + part * 4);
        acc.x += v.x * c; acc.y += v.y * c; acc.z += v.z * c; acc.w += v.w * c;
    }

    float sl = din * din;
    float4 h = *reinterpret_cast<const float4*>(g_h2 + node * NCP2 + part * 4);
    float* pool = g_pool + g * NC;

    float res[4] = { acc.x + h.x * sl, acc.y + h.y * sl,
                     acc.z + h.z * sl, acc.w + h.w * sl };
#pragma unroll
    for (int c = 0; c < 4; c++) {
        int col = part * 4 + c;
        if (col < NC) atomicAdd(pool + col, res[c] + b2[col]);
    }
    if (part == 0) {
        atomicAdd(&g_gcnt[g], 1.0f);
        g_cnt_i[node] = 0;                    // self-clean for next call
    }
}

// ---------------- finalize: mean + log_softmax (+ self-clean pool) ----------------------
__global__ void k_softmax(float* __restrict__ out) {
    int g = threadIdx.x;
    if (g >= NG) return;
    float cnt = fmaxf(g_gcnt[g], 1.0f);
    float p[NC];
    float m = -1e30f;
#pragma unroll
    for (int o = 0; o < NC; o++) { p[o] = g_pool[g * NC + o] / cnt; m = fmaxf(m, p[o]); }
    float s = 0.f;
#pragma unroll
    for (int o = 0; o < NC; o++) s += __expf(p[o] - m);
    float l = logf(s);
#pragma unroll
    for (int o = 0; o < NC; o++) {
        out[g * NC + o] = p[o] - m - l;
        g_pool[g * NC + o] = 0.f;             // self-clean for next call
    }
    g_gcnt[g] = 0.f;
}

// ---------------- launcher ----------------------------------------------------------------
extern "C" void kernel_launch(void* const* d_in, const int* in_sizes, int n_in,
                              void* d_out, int out_size) {
    const float* x     = (const float*)d_in[0];
    const int*   ei    = (const int*)d_in[1];    // int32 (jax default int)
    const int*   batch = (const int*)d_in[2];
    const float* W1    = (const float*)d_in[3];
    const float* b1    = (const float*)d_in[4];
    const float* W2    = (const float*)d_in[5];
    const float* b2    = (const float*)d_in[6];
    float* out = (float*)d_out;

    const int TB = 256;
    const int nodeBlocks  = (N_NODES + TB - 1) / TB;          // 391
    const int node4Blocks = (4 * N_NODES + TB - 1) / TB;      // 1563
    const int fillBlocks  = (N_EDGES / 4 + TB - 1) / TB;      // 3125

    k_pre1<<<PRE1_BLOCKS, TB>>>(x, W1, ei);           // launch 1
    k_scan_block<<<N_SCAN_BLOCKS, SCAN_BLK>>>();      // launch 2
    k_scan_finish<<<nodeBlocks, TB>>>();              // launch 3
    k_fill<<<fillBlocks, TB>>>(ei);                   // launch 4  <- ncu slot
    k_gather1<<<node4Blocks, TB>>>(b1, W2);           // launch 5
    k_gather2<<<node4Blocks, TB>>>(b2, batch);        // launch 6
    k_softmax<<<1, 64>>>(out);                        // launch 7
}

// round 15
// speedup vs baseline: 1.7658x; 1.0035x over previous
#include <cuda_runtime.h>

#define N_NODES 100000
#define N_EDGES 3200000
#define NFEAT 128
#define HID 16
#define NC 10
#define NCP2 16   // h2 rows padded to 16 floats (64B, 4x float4)
#define NG 64
#define SCAN_BLK 1024
#define N_SCAN_BLOCKS ((N_NODES + SCAN_BLK - 1) / SCAN_BLK)   // 98

#define GEMM1_BLOCKS ((N_NODES + 63) / 64)          // 1563 = 3 * 521
#define PRE1_QUADS   (GEMM1_BLOCKS / 3)             // 521 (3 gemm + 1 hist per quad)
#define PRE1_BLOCKS  (PRE1_QUADS * 4)               // 2084

// ---------------- device scratch --------------------------------------------------
__device__ int   g_cnt_i   [N_NODES];      // in-degree histogram over dst (self-cleaned)
__device__ int   g_rowstart[N_NODES];      // exclusive prefix sum
__device__ int   g_cur     [N_NODES];      // fill cursors (re-inited each call)
__device__ int   g_bsum    [N_SCAN_BLOCKS];
__device__ int2  g_csr     [N_EDGES];      // {src, __float_as_int(dinv[src])}
__device__ float g_dinv    [N_NODES];
__device__ float g_h1      [N_NODES * HID];    // x @ W1
__device__ float g_h2      [N_NODES * NCP2];   // relu(conv1) @ W2, padded
__device__ float g_pool    [NG * NC];          // self-cleaned in softmax
__device__ float g_gcnt    [NG];               // self-cleaned in softmax

// ---------------- fused: GEMM1 (3/4 of blocks) + dst-histogram (1/4) ---------------
// R11 form: hist atomics are fire-and-forget (REDG), return value unused.
__global__ __launch_bounds__(256) void k_pre1(const float* __restrict__ x,
                                              const float* __restrict__ W1,
                                              const int* __restrict__ ei) {
    __shared__ float sx[64 * 129];
    __shared__ float sW[NFEAT * HID];

    int b = blockIdx.x;
    int tid = threadIdx.x;

    if ((b & 3) == 3) {
        // ---- histogram role: grid-stride over dst half as int4 ----
        const int4* dst4 = reinterpret_cast<const int4*>(ei + N_EDGES);
        int n4 = N_EDGES / 4;
        int i = (b >> 2) * 256 + tid;
        int stride = PRE1_QUADS * 256;
        for (; i < n4; i += stride) {
            int4 d = dst4[i];
            atomicAdd(&g_cnt_i[d.x], 1);
            atomicAdd(&g_cnt_i[d.y], 1);
            atomicAdd(&g_cnt_i[d.z], 1);
            atomicAdd(&g_cnt_i[d.w], 1);
        }
        return;
    }

    // ---- gemm1 role ----
    int gb = (b >> 2) * 3 + (b & 3);      // 0..GEMM1_BLOCKS-1
    int node0 = gb * 64;

    for (int j = tid; j < NFEAT * HID; j += 256) sW[j] = W1[j];

    int nvalid = N_NODES - node0; if (nvalid > 64) nvalid = 64;
    for (int j = tid; j < 64 * NFEAT; j += 256) {
        int r = j / NFEAT, c = j % NFEAT;
        sx[r * 129 + c] = (r < nvalid) ? x[(long long)(node0 + r) * NFEAT + c] : 0.f;
    }
    __syncthreads();

    int n  = tid & 63;
    int og = tid >> 6;
    if (n >= nvalid) return;

    float4 acc0 = make_float4(0.f, 0.f, 0.f, 0.f);
    float4 acc1 = make_float4(0.f, 0.f, 0.f, 0.f);
    const float4* sW4 = reinterpret_cast<const float4*>(sW);
    const float*  xr  = sx + n * 129;
#pragma unroll 8
    for (int k = 0; k < NFEAT; k += 2) {
        float xv0 = xr[k], xv1 = xr[k + 1];
        float4 w0 = sW4[k * 4 + og];
        float4 w1 = sW4[(k + 1) * 4 + og];
        acc0.x += xv0 * w0.x; acc0.y += xv0 * w0.y;
        acc0.z += xv0 * w0.z; acc0.w += xv0 * w0.w;
        acc1.x += xv1 * w1.x; acc1.y += xv1 * w1.y;
        acc1.z += xv1 * w1.z; acc1.w += xv1 * w1.w;
    }
    float4 acc = make_float4(acc0.x + acc1.x, acc0.y + acc1.y,
                             acc0.z + acc1.z, acc0.w + acc1.w);
    reinterpret_cast<float4*>(g_h1 + (node0 + n) * HID)[og] = acc;
}

// ---------------- scan phase 1 (+ dinv) ----------------------------------------------
__global__ __launch_bounds__(SCAN_BLK) void k_scan_block() {
    __shared__ int sh[SCAN_BLK];
    int t = threadIdx.x;
    int i = blockIdx.x * SCAN_BLK + t;
    int v = (i < N_NODES) ? g_cnt_i[i] : 0;
    if (i < N_NODES) g_dinv[i] = rsqrtf((float)v + 1.0f);
    sh[t] = v;
    __syncthreads();
#pragma unroll
    for (int off = 1; off < SCAN_BLK; off <<= 1) {
        int add = (t >= off) ? sh[t - off] : 0;
        __syncthreads();
        sh[t] += add;
        __syncthreads();
    }
    if (i < N_NODES) g_rowstart[i] = sh[t] - v;          // block-local exclusive
    if (t == SCAN_BLK - 1) g_bsum[blockIdx.x] = sh[t];
}

// ---------------- scan finish: per-block redundant bsum scan + offset + cursor init ---
__global__ __launch_bounds__(256) void k_scan_finish() {
    __shared__ int sb[128];
    int t = threadIdx.x;
    if (t < 128) sb[t] = (t < N_SCAN_BLOCKS) ? g_bsum[t] : 0;
    __syncthreads();
#pragma unroll
    for (int off = 1; off < 128; off <<= 1) {
        int add = (t < 128 && t >= off) ? sb[t - off] : 0;
        __syncthreads();
        if (t < 128) sb[t] += add;
        __syncthreads();
    }
    int i = blockIdx.x * 256 + t;
    if (i < N_NODES) {
        int blk = i >> 10;
        int excl = sb[blk] - g_bsum[blk];       // inclusive -> exclusive
        int rs = g_rowstart[i] + excl;
        g_rowstart[i] = rs;
        g_cur[i] = rs;
    }
}

// ---------------- CSR fill: 4 edges/thread via int4 (MLP=4), cursor atomics ------------
__global__ __launch_bounds__(256) void k_fill(const int* __restrict__ ei) {
    const int4* s4p = reinterpret_cast<const int4*>(ei);
    const int4* d4p = reinterpret_cast<const int4*>(ei + N_EDGES);
    int i = blockIdx.x * blockDim.x + threadIdx.x;
    int n4 = N_EDGES / 4;
    if (i >= n4) return;
    int4 s = s4p[i];
    int4 d = d4p[i];
    float a0 = g_dinv[s.x], a1 = g_dinv[s.y], a2 = g_dinv[s.z], a3 = g_dinv[s.w];
    int p0 = atomicAdd(&g_cur[d.x], 1);
    int p1 = atomicAdd(&g_cur[d.y], 1);
    int p2 = atomicAdd(&g_cur[d.z], 1);
    int p3 = atomicAdd(&g_cur[d.w], 1);
    g_csr[p0] = make_int2(s.x, __float_as_int(a0));
    g_csr[p1] = make_int2(s.y, __float_as_int(a1));
    g_csr[p2] = make_int2(s.z, __float_as_int(a2));
    g_csr[p3] = make_int2(s.w, __float_as_int(a3));
}

// ---------------- gather1 + combine1 + relu + GEMM2 (4 threads / node, 8-deep) ---------
__global__ __launch_bounds__(256) void k_gather1(const float* __restrict__ b1,
                                                 const float* __restrict__ W2) {
    __shared__ float sW2[HID * NC];
    int tid = threadIdx.x;
    if (tid < HID * NC) sW2[tid] = W2[tid];
    __syncthreads();

    int gt = blockIdx.x * blockDim.x + tid;
    int node = gt >> 2;
    bool valid = node < N_NODES;
    if (!valid) node = N_NODES - 1;          // clamp; keep lanes alive for shfl
    int part = tid & 3;

    int rs  = g_rowstart[node];
    int deg = g_cnt_i[node];
    float din = g_dinv[node];

    const int2* sp = g_csr + rs;
    float4 acc = make_float4(0.f, 0.f, 0.f, 0.f);

    int j = 0;
    // ---- 8-deep main loop: 8 independent row loads in flight per thread ----
    for (; j + 16 <= deg; j += 8) {
        int2 p0 = sp[j + 0], p1 = sp[j + 1], p2 = sp[j + 2], p3 = sp[j + 3];
        int2 p4 = sp[j + 4], p5 = sp[j + 5], p6 = sp[j + 6], p7 = sp[j + 7];
        float4 v0 = *reinterpret_cast<const float4*>(g_h1 + p0.x * HID + part * 4);
        float4 v1 = *reinterpret_cast<const float4*>(g_h1 + p1.x * HID + part * 4);
        float4 v2 = *reinterpret_cast<const float4*>(g_h1 + p2.x * HID + part * 4);
        float4 v3 = *reinterpret_cast<const float4*>(g_h1 + p3.x * HID + part * 4);
        float4 v4 = *reinterpret_cast<const float4*>(g_h1 + p4.x * HID + part * 4);
        float4 v5 = *reinterpret_cast<const float4*>(g_h1 + p5.x * HID + part * 4);
        float4 v6 = *reinterpret_cast<const float4*>(g_h1 + p6.x * HID + part * 4);
        float4 v7 = *reinterpret_cast<const float4*>(g_h1 + p7.x * HID + part * 4);
        float c0 = din * __int_as_float(p0.y);
        float c1 = din * __int_as_float(p1.y);
        float c2 = din * __int_as_float(p2.y);
        float c3 = din * __int_as_float(p3.y);
        float c4 = din * __int_as_float(p4.y);
        float c5 = din * __int_as_float(p5.y);
        float c6 = din * __int_as_float(p6.y);
        float c7 = din * __int_as_float(p7.y);
        acc.x += v0.x * c0; acc.y += v0.y * c0; acc.z += v0.z * c0; acc.w += v0.w * c0;
        acc.x += v1.x * c1; acc.y += v1.y * c1; acc.z += v1.z * c1; acc.w += v1.w * c1;
        acc.x += v2.x * c2; acc.y += v2.y * c2; acc.z += v2.z * c2; acc.w += v2.w * c2;
        acc.x += v3.x * c3; acc.y += v3.y * c3; acc.z += v3.z * c3; acc.w += v3.w * c3;
        acc.x += v4.x * c4; acc.y += v4.y * c4; acc.z += v4.z * c4; acc.w += v4.w * c4;
        acc.x += v5.x * c5; acc.y += v5.y * c5; acc.z += v5.z * c5; acc.w += v5.w * c5;
        acc.x += v6.x * c6; acc.y += v6.y * c6; acc.z += v6.z * c6; acc.w += v6.w * c6;
        acc.x += v7.x * c7; acc.y += v7.y * c7; acc.z += v7.z * c7; acc.w += v7.w * c7;
    }
    // ---- 4-wide cleanup ----
    for (; j + 4 <= deg; j += 4) {
        int2 p0 = sp[j + 0], p1 = sp[j + 1], p2 = sp[j + 2], p3 = sp[j + 3];
        float4 v0 = *reinterpret_cast<const float4*>(g_h1 + p0.x * HID + part * 4);
        float4 v1 = *reinterpret_cast<const float4*>(g_h1 + p1.x * HID + part * 4);
        float4 v2 = *reinterpret_cast<const float4*>(g_h1 + p2.x * HID + part * 4);
        float4 v3 = *reinterpret_cast<const float4*>(g_h1 + p3.x * HID + part * 4);
        float c0 = din * __int_as_float(p0.y);
        float c1 = din * __int_as_float(p1.y);
        float c2 = din * __int_as_float(p2.y);
        float c3 = din * __int_as_float(p3.y);
        acc.x += v0.x * c0; acc.y += v0.y * c0; acc.z += v0.z * c0; acc.w += v0.w * c0;
        acc.x += v1.x * c1; acc.y += v1.y * c1; acc.z += v1.z * c1; acc.w += v1.w * c1;
        acc.x += v2.x * c2; acc.y += v2.y * c2; acc.z += v2.z * c2; acc.w += v2.w * c2;
        acc.x += v3.x * c3; acc.y += v3.y * c3; acc.z += v3.z * c3; acc.w += v3.w * c3;
    }
    for (; j < deg; j++) {
        int2 p = sp[j];
        float c = din * __int_as_float(p.y);
        float4 v = *reinterpret_cast<const float4*>(g_h1 + p.x * HID + part * 4);
        acc.x += v.x * c; acc.y += v.y * c; acc.z += v.z * c; acc.w += v.w * c;
    }

    // combine + relu -> this thread's 4-wide slice of hr
    float sl = din * din;
    float4 h = *reinterpret_cast<const float4*>(g_h1 + node * HID + part * 4);
    float4 b = reinterpret_cast<const float4*>(b1)[part];
    float4 a;
    a.x = fmaxf(acc.x + h.x * sl + b.x, 0.f);
    a.y = fmaxf(acc.y + h.y * sl + b.y, 0.f);
    a.z = fmaxf(acc.z + h.z * sl + b.z, 0.f);
    a.w = fmaxf(acc.w + h.w * sl + b.w, 0.f);

    // exchange the 16-wide hr row among the 4 lanes of this node
    float hr[HID];
    unsigned lanebase = (unsigned)(tid & 31) & ~3u;
#pragma unroll
    for (int q = 0; q < 4; q++) {
        hr[q * 4 + 0] = __shfl_sync(0xffffffffu, a.x, lanebase + q);
        hr[q * 4 + 1] = __shfl_sync(0xffffffffu, a.y, lanebase + q);
        hr[q * 4 + 2] = __shfl_sync(0xffffffffu, a.z, lanebase + q);
        hr[q * 4 + 3] = __shfl_sync(0xffffffffu, a.w, lanebase + q);
    }

    // gemm2: this thread computes output cols [part*4, part*4+4)
    float4 o = make_float4(0.f, 0.f, 0.f, 0.f);
    float* op = &o.x;
#pragma unroll
    for (int c = 0; c < 4; c++) {
        int col = part * 4 + c;
        if (col < NC) {
            float s = 0.f;
#pragma unroll
            for (int k = 0; k < HID; k++) s += hr[k] * sW2[k * NC + col];
            op[c] = s;
        }
    }
    if (valid)
        *reinterpret_cast<float4*>(g_h2 + node * NCP2 + part * 4) = o;
}

// ---------------- gather2 + combine2 + mean-pool (4 threads / node, 8-deep pipeline) ---
__global__ __launch_bounds__(256) void k_gather2(const float* __restrict__ b2,
                                                 const int* __restrict__ batch) {
    int gt = blockIdx.x * blockDim.x + threadIdx.x;
    int node = gt >> 2;
    if (node >= N_NODES) return;
    int part = gt & 3;

    int rs  = g_rowstart[node];
    int deg = g_cnt_i[node];
    float din = g_dinv[node];
    int g = batch[node];

    const int2* sp = g_csr + rs;
    float4 acc = make_float4(0.f, 0.f, 0.f, 0.f);

    int j = 0;
    // ---- 8-deep main loop: 8 independent row loads in flight per thread ----
    for (; j + 16 <= deg; j += 8) {
        int2 p0 = sp[j + 0], p1 = sp[j + 1], p2 = sp[j + 2], p3 = sp[j + 3];
        int2 p4 = sp[j + 4], p5 = sp[j + 5], p6 = sp[j + 6], p7 = sp[j + 7];
        float4 v0 = *reinterpret_cast<const float4*>(g_h2 + p0.x * NCP2 + part * 4);
        float4 v1 = *reinterpret_cast<const float4*>(g_h2 + p1.x * NCP2 + part * 4);
        float4 v2 = *reinterpret_cast<const float4*>(g_h2 + p2.x * NCP2 + part * 4);
        float4 v3 = *reinterpret_cast<const float4*>(g_h2 + p3.x * NCP2 + part * 4);
        float4 v4 = *reinterpret_cast<const float4*>(g_h2 + p4.x * NCP2 + part * 4);
        float4 v5 = *reinterpret_cast<const float4*>(g_h2 + p5.x * NCP2 + part * 4);
        float4 v6 = *reinterpret_cast<const float4*>(g_h2 + p6.x * NCP2 + part * 4);
        float4 v7 = *reinterpret_cast<const float4*>(g_h2 + p7.x * NCP2 + part * 4);
        float c0 = din * __int_as_float(p0.y);
        float c1 = din * __int_as_float(p1.y);
        float c2 = din * __int_as_float(p2.y);
        float c3 = din * __int_as_float(p3.y);
        float c4 = din * __int_as_float(p4.y);
        float c5 = din * __int_as_float(p5.y);
        float c6 = din * __int_as_float(p6.y);
        float c7 = din * __int_as_float(p7.y);
        acc.x += v0.x * c0; acc.y += v0.y * c0; acc.z += v0.z * c0; acc.w += v0.w * c0;
        acc.x += v1.x * c1; acc.y += v1.y * c1; acc.z += v1.z * c1; acc.w += v1.w * c1;
        acc.x += v2.x * c2; acc.y += v2.y * c2; acc.z += v2.z * c2; acc.w += v2.w * c2;
        acc.x += v3.x * c3; acc.y += v3.y * c3; acc.z += v3.z * c3; acc.w += v3.w * c3;
        acc.x += v4.x * c4; acc.y += v4.y * c4; acc.z += v4.z * c4; acc.w += v4.w * c4;
        acc.x += v5.x * c5; acc.y += v5.y * c5; acc.z += v5.z * c5; acc.w += v5.w * c5;
        acc.x += v6.x * c6; acc.y += v6.y * c6; acc.z += v6.z * c6; acc.w += v6.w * c6;
        acc.x += v7.x * c7; acc.y += v7.y * c7; acc.z += v7.z * c7; acc.w += v7.w * c7;
    }
    // ---- 4-wide cleanup ----
    for (; j + 4 <= deg; j += 4) {
        int2 p0 = sp[j + 0], p1 = sp[j + 1], p2 = sp[j + 2], p3 = sp[j + 3];
        float4 v0 = *reinterpret_cast<const float4*>(g_h2 + p0.x * NCP2 + part * 4);
        float4 v1 = *reinterpret_cast<const float4*>(g_h2 + p1.x * NCP2 + part * 4);
        float4 v2 = *reinterpret_cast<const float4*>(g_h2 + p2.x * NCP2 + part * 4);
        float4 v3 = *reinterpret_cast<const float4*>(g_h2 + p3.x * NCP2 + part * 4);
        float c0 = din * __int_as_float(p0.y);
        float c1 = din * __int_as_float(p1.y);
        float c2 = din * __int_as_float(p2.y);
        float c3 = din * __int_as_float(p3.y);
        acc.x += v0.x * c0; acc.y += v0.y * c0; acc.z += v0.z * c0; acc.w += v0.w * c0;
        acc.x += v1.x * c1; acc.y += v1.y * c1; acc.z += v1.z * c1; acc.w += v1.w * c1;
        acc.x += v2.x * c2; acc.y += v2.y * c2; acc.z += v2.z * c2; acc.w += v2.w * c2;
        acc.x += v3.x * c3; acc.y += v3.y * c3; acc.z += v3.z * c3; acc.w += v3.w * c3;
    }
    for (; j < deg; j++) {
        int2 p = sp[j];
        float c = din * __int_as_float(p.y);
        float4 v = *reinterpret_cast<const float4*>(g_h2 + p.x * NCP2 + part * 4);
        acc.x += v.x * c; acc.y += v.y * c; acc.z += v.z * c; acc.w += v.w * c;
    }

    float sl = din * din;
    float4 h = *reinterpret_cast<const float4*>(g_h2 + node * NCP2 + part * 4);
    float* pool = g_pool + g * NC;

    float res[4] = { acc.x + h.x * sl, acc.y + h.y * sl,
                     acc.z + h.z * sl, acc.w + h.w * sl };
#pragma unroll
    for (int c = 0; c < 4; c++) {
        int col = part * 4 + c;
        if (col < NC) atomicAdd(pool + col, res[c] + b2[col]);
    }
    if (part == 0) {
        atomicAdd(&g_gcnt[g], 1.0f);
        g_cnt_i[node] = 0;                    // self-clean for next call
    }
}

// ---------------- finalize: mean + log_softmax (+ self-clean pool) ----------------------
__global__ void k_softmax(float* __restrict__ out) {
    int g = threadIdx.x;
    if (g >= NG) return;
    float cnt = fmaxf(g_gcnt[g], 1.0f);
    float p[NC];
    float m = -1e30f;
#pragma unroll
    for (int o = 0; o < NC; o++) { p[o] = g_pool[g * NC + o] / cnt; m = fmaxf(m, p[o]); }
    float s = 0.f;
#pragma unroll
    for (int o = 0; o < NC; o++) s += __expf(p[o] - m);
    float l = logf(s);
#pragma unroll
    for (int o = 0; o < NC; o++) {
        out[g * NC + o] = p[o] - m - l;
        g_pool[g * NC + o] = 0.f;             // self-clean for next call
    }
    g_gcnt[g] = 0.f;
}

// ---------------- launcher ----------------------------------------------------------------
extern "C" void kernel_launch(void* const* d_in, const int* in_sizes, int n_in,
                              void* d_out, int out_size) {
    const float* x     = (const float*)d_in[0];
    const int*   ei    = (const int*)d_in[1];    // int32 (jax default int)
    const int*   batch = (const int*)d_in[2];
    const float* W1    = (const float*)d_in[3];
    const float* b1    = (const float*)d_in[4];
    const float* W2    = (const float*)d_in[5];
    const float* b2    = (const float*)d_in[6];
    float* out = (float*)d_out;

    const int TB = 256;
    const int nodeBlocks  = (N_NODES + TB - 1) / TB;          // 391
    const int node4Blocks = (4 * N_NODES + TB - 1) / TB;      // 1563
    const int fillBlocks  = (N_EDGES / 4 + TB - 1) / TB;      // 3125

    k_pre1<<<PRE1_BLOCKS, TB>>>(x, W1, ei);           // launch 1
    k_scan_block<<<N_SCAN_BLOCKS, SCAN_BLK>>>();      // launch 2
    k_scan_finish<<<nodeBlocks, TB>>>();              // launch 3
    k_fill<<<fillBlocks, TB>>>(ei);                   // launch 4  <- ncu slot
    k_gather1<<<node4Blocks, TB>>>(b1, W2);           // launch 5
    k_gather2<<<node4Blocks, TB>>>(b2, batch);        // launch 6
    k_softmax<<<1, 64>>>(out);                        // launch 7
}